// round 1
// baseline (speedup 1.0000x reference)
#include <cuda_runtime.h>
#include <cstdint>

// Problem constants (fixed by dataset)
#define NV 100000
#define EV 1600000
#define FV 512
#define HV 256
#define NB_SCAN ((NV + 255) / 256)   // 391

// ---------------- scratch (static device globals; no allocation) ----------------
__device__ int   g_out_deg[NV];
__device__ int   g_in_deg[NV];
__device__ float g_norm_src[NV];
__device__ float g_norm_dst[NV];
__device__ int   g_offsets[NV];
__device__ int   g_cursor[NV];
__device__ int   g_part[NB_SCAN];
__device__ int   g_sorted_src[EV];
__device__ __align__(16) float g_y[(size_t)NV * HV];   // pre-aggregation activations
__device__ __align__(16) float g_h[(size_t)NV * HV];   // post-aggregation activations
__device__ float g_pooled[3 * HV];
__device__ float g_fd[2 * FV];

// ---------------- init / degrees / norms ----------------
__global__ void k_init() {
    int i = blockIdx.x * blockDim.x + threadIdx.x;
    if (i < NV) { g_out_deg[i] = 0; g_in_deg[i] = 0; g_cursor[i] = 0; }
    if (i < HV) { g_pooled[i] = 0.0f; g_pooled[HV + i] = __int_as_float(0xff800000); } // -inf
}

__global__ void k_deg(const int* __restrict__ src, const int* __restrict__ dst) {
    int e = blockIdx.x * blockDim.x + threadIdx.x;
    if (e < EV) {
        atomicAdd(&g_out_deg[src[e]], 1);
        atomicAdd(&g_in_deg[dst[e]], 1);
    }
}

__global__ void k_norm() {
    int i = blockIdx.x * blockDim.x + threadIdx.x;
    if (i < NV) {
        g_norm_src[i] = rsqrtf(fmaxf((float)g_out_deg[i], 1.0f));
        g_norm_dst[i] = rsqrtf(fmaxf((float)g_in_deg[i], 1.0f));
    }
}

// ---------------- exclusive scan of in_deg -> offsets (3 kernels) ----------------
__global__ void k_scan1() {
    __shared__ int s[256];
    int t = threadIdx.x;
    int i = blockIdx.x * 256 + t;
    int v = (i < NV) ? g_in_deg[i] : 0;
    s[t] = v;
    __syncthreads();
    #pragma unroll
    for (int off = 1; off < 256; off <<= 1) {
        int x = (t >= off) ? s[t - off] : 0;
        __syncthreads();
        s[t] += x;
        __syncthreads();
    }
    if (i < NV) g_offsets[i] = s[t] - v;        // exclusive within block
    if (t == 255) g_part[blockIdx.x] = s[255];  // block total
}

__global__ void k_scan2() {
    if (threadIdx.x == 0) {
        int acc = 0;
        for (int b = 0; b < NB_SCAN; b++) { int v = g_part[b]; g_part[b] = acc; acc += v; }
    }
}

__global__ void k_scan3() {
    int t = threadIdx.x;
    int i = blockIdx.x * 256 + t;
    if (i < NV) g_offsets[i] += g_part[blockIdx.x];
}

// ---------------- scatter edges into CSR-by-dst ----------------
__global__ void k_scatter(const int* __restrict__ src, const int* __restrict__ dst) {
    int e = blockIdx.x * blockDim.x + threadIdx.x;
    if (e < EV) {
        int d = dst[e];
        int p = atomicAdd(&g_cursor[d], 1);
        g_sorted_src[g_offsets[d] + p] = src[e];
    }
}

// ---------------- SGEMM: C[M,256] = (A * norm_src[:,None]) @ B[K,256] ----------------
// 128x128 block tile, 8x8 per thread, BK=16
__global__ __launch_bounds__(256) void k_gemm(const float* __restrict__ A,
                                              const float* __restrict__ B,
                                              float* __restrict__ C,
                                              int M, int K) {
    const int BM = 128, BN = 128, BK = 16;
    __shared__ float As[BK][BM + 1];
    __shared__ float Bs[BK][BN];

    int tid  = threadIdx.x;
    int brow = blockIdx.y * BM;
    int bcol = blockIdx.x * BN;
    int tr   = tid >> 4;   // 0..15
    int tc   = tid & 15;   // 0..15

    // A-load mapping (constant across k-loop)
    int aIdx0 = tid;          // float4 index 0..255
    int aIdx1 = tid + 256;    // 256..511
    int arow0 = aIdx0 >> 2, ac40 = aIdx0 & 3;
    int arow1 = aIdx1 >> 2, ac41 = aIdx1 & 3;
    int gr0 = brow + arow0, gr1 = brow + arow1;
    bool v0 = gr0 < M, v1 = gr1 < M;
    float s0 = v0 ? g_norm_src[gr0] : 0.0f;
    float s1 = v1 ? g_norm_src[gr1] : 0.0f;
    const float* Aptr0 = A + (size_t)(v0 ? gr0 : 0) * K;
    const float* Aptr1 = A + (size_t)(v1 ? gr1 : 0) * K;

    // B-load mapping
    int brow0 = aIdx0 >> 5, bc40 = aIdx0 & 31;
    int brow1 = aIdx1 >> 5, bc41 = aIdx1 & 31;

    float acc[8][8];
    #pragma unroll
    for (int i = 0; i < 8; i++)
        #pragma unroll
        for (int j = 0; j < 8; j++) acc[i][j] = 0.0f;

    for (int k0 = 0; k0 < K; k0 += BK) {
        // load A tile (scaled by norm_src), transposed into As
        {
            float4 a0 = v0 ? *(const float4*)(Aptr0 + k0 + ac40 * 4) : make_float4(0,0,0,0);
            float4 a1 = v1 ? *(const float4*)(Aptr1 + k0 + ac41 * 4) : make_float4(0,0,0,0);
            As[ac40*4+0][arow0] = a0.x * s0; As[ac40*4+1][arow0] = a0.y * s0;
            As[ac40*4+2][arow0] = a0.z * s0; As[ac40*4+3][arow0] = a0.w * s0;
            As[ac41*4+0][arow1] = a1.x * s1; As[ac41*4+1][arow1] = a1.y * s1;
            As[ac41*4+2][arow1] = a1.z * s1; As[ac41*4+3][arow1] = a1.w * s1;
        }
        // load B tile
        {
            float4 b0 = *(const float4*)(B + (size_t)(k0 + brow0) * HV + bcol + bc40 * 4);
            float4 b1 = *(const float4*)(B + (size_t)(k0 + brow1) * HV + bcol + bc41 * 4);
            *(float4*)&Bs[brow0][bc40 * 4] = b0;
            *(float4*)&Bs[brow1][bc41 * 4] = b1;
        }
        __syncthreads();

        #pragma unroll
        for (int kk = 0; kk < BK; kk++) {
            float a[8], b[8];
            #pragma unroll
            for (int i = 0; i < 8; i++) a[i] = As[kk][tr * 8 + i];
            #pragma unroll
            for (int j = 0; j < 8; j++) b[j] = Bs[kk][tc * 8 + j];
            #pragma unroll
            for (int i = 0; i < 8; i++)
                #pragma unroll
                for (int j = 0; j < 8; j++) acc[i][j] += a[i] * b[j];
        }
        __syncthreads();
    }

    #pragma unroll
    for (int i = 0; i < 8; i++) {
        int r = brow + tr * 8 + i;
        if (r < M) {
            float4 o0 = make_float4(acc[i][0], acc[i][1], acc[i][2], acc[i][3]);
            float4 o1 = make_float4(acc[i][4], acc[i][5], acc[i][6], acc[i][7]);
            float* cp = C + (size_t)r * HV + bcol + tc * 8;
            *(float4*)(cp)     = o0;
            *(float4*)(cp + 4) = o1;
        }
    }
}

// ---------------- aggregation: O[n] = leaky( norm_dst[n]*sum_{e in CSR(n)} Y[src_e] + bias ) ----
__global__ void k_agg(const float* __restrict__ Y, const float* __restrict__ bias,
                      float* __restrict__ O) {
    int node = blockIdx.x;
    int t = threadIdx.x;            // 64 threads, 4 cols each via float4
    int start = g_offsets[node];
    int cnt   = g_in_deg[node];
    float4 acc = make_float4(0, 0, 0, 0);
    for (int e = 0; e < cnt; e++) {
        int s = g_sorted_src[start + e];
        float4 v = *(const float4*)(Y + (size_t)s * HV + t * 4);
        acc.x += v.x; acc.y += v.y; acc.z += v.z; acc.w += v.w;
    }
    float nd = g_norm_dst[node];
    float4 bb = *(const float4*)(bias + t * 4);
    float4 o;
    o.x = acc.x * nd + bb.x;  o.x = (o.x >= 0.0f) ? o.x : 0.01f * o.x;
    o.y = acc.y * nd + bb.y;  o.y = (o.y >= 0.0f) ? o.y : 0.01f * o.y;
    o.z = acc.z * nd + bb.z;  o.z = (o.z >= 0.0f) ? o.z : 0.01f * o.z;
    o.w = acc.w * nd + bb.w;  o.w = (o.w >= 0.0f) ? o.w : 0.01f * o.w;
    *(float4*)(O + (size_t)node * HV + t * 4) = o;
}

// ---------------- pooling: column-wise sum and max of g_h ----------------
__device__ __forceinline__ void atomicMaxF(float* addr, float val) {
    int* ia = (int*)addr;
    int old = *ia;
    while (__int_as_float(old) < val) {
        int assumed = old;
        old = atomicCAS(ia, assumed, __float_as_int(val));
        if (old == assumed) break;
    }
}

__global__ void k_pool() {
    int t = threadIdx.x;  // 256
    float sum = 0.0f;
    float mx  = __int_as_float(0xff800000);
    for (int r = blockIdx.x; r < NV; r += gridDim.x) {
        float v = g_h[(size_t)r * HV + t];
        sum += v;
        mx = fmaxf(mx, v);
    }
    atomicAdd(&g_pooled[t], sum);
    atomicMaxF(&g_pooled[HV + t], mx);
}

__global__ void k_pick(const int* __restrict__ node_index) {
    int t = threadIdx.x;  // 256
    int ni = node_index[0];
    g_pooled[2 * HV + t] = g_h[(size_t)ni * HV + t];
}

// ---------------- head GEMV: fd[1024] = pooled[768] @ Wg[768,1024] + bg ----------------
__global__ void k_gemv(const float* __restrict__ Wg, const float* __restrict__ bg) {
    __shared__ float sp[3 * HV];
    int t = threadIdx.x;  // 256, grid 4
    for (int i = t; i < 3 * HV; i += 256) sp[i] = g_pooled[i];
    __syncthreads();
    int j = blockIdx.x * 256 + t;
    float acc = bg[j];
    #pragma unroll 8
    for (int k = 0; k < 3 * HV; k++) acc += sp[k] * Wg[(size_t)k * (2 * FV) + j];
    g_fd[j] = acc;
}

// ---------------- epilogue: reparam + log_prob ----------------
__global__ void k_final(const float* __restrict__ eps, float* __restrict__ out) {
    __shared__ float red[FV];
    int t = threadIdx.x;  // 512
    float mu = g_fd[t];
    float sg = fabsf(g_fd[FV + t]);
    float fn = mu + sg * eps[t];
    out[t]          = fn;   // feat_new
    out[FV + t]     = mu;   // mu
    out[2 * FV + t] = sg;   // sigma
    float z = (fn - mu) / sg;
    const float half_log2pi = 0.9189385332046727f;  // 0.5*log(2*pi)
    float term = -0.5f * z * z - logf(sg) - half_log2pi;
    red[t] = term;
    __syncthreads();
    #pragma unroll
    for (int o = 256; o > 0; o >>= 1) {
        if (t < o) red[t] += red[t + o];
        __syncthreads();
    }
    if (t == 0) out[3 * FV] = red[0] / (float)FV;  // log_prob
}

// ---------------- launch ----------------
extern "C" void kernel_launch(void* const* d_in, const int* in_sizes, int n_in,
                              void* d_out, int out_size) {
    const float* feat       = (const float*)d_in[0];
    const int*   src        = (const int*)  d_in[1];
    const int*   dst        = (const int*)  d_in[2];
    const int*   node_index = (const int*)  d_in[3];
    const float* W1         = (const float*)d_in[4];
    const float* b1         = (const float*)d_in[5];
    const float* W2         = (const float*)d_in[6];
    const float* b2         = (const float*)d_in[7];
    const float* Wg         = (const float*)d_in[8];
    const float* bg         = (const float*)d_in[9];
    const float* eps        = (const float*)d_in[10];
    float*       out        = (float*)d_out;

    void *yp_v, *hp_v;
    cudaGetSymbolAddress(&yp_v, g_y);
    cudaGetSymbolAddress(&hp_v, g_h);
    float* yp = (float*)yp_v;
    float* hp = (float*)hp_v;

    k_init<<<(NV + 255) / 256, 256>>>();
    k_deg<<<(EV + 255) / 256, 256>>>(src, dst);
    k_norm<<<(NV + 255) / 256, 256>>>();
    k_scan1<<<NB_SCAN, 256>>>();
    k_scan2<<<1, 32>>>();
    k_scan3<<<NB_SCAN, 256>>>();
    k_scatter<<<(EV + 255) / 256, 256>>>(src, dst);

    dim3 gemm_grid(2, (NV + 127) / 128);
    // layer 1: y = (feat * norm_src) @ W1 ; h = leaky(agg(y)*norm_dst + b1)
    k_gemm<<<gemm_grid, 256>>>(feat, W1, yp, NV, FV);
    k_agg<<<NV, 64>>>(yp, b1, hp);
    // layer 2
    k_gemm<<<gemm_grid, 256>>>(hp, W2, yp, NV, HV);
    k_agg<<<NV, 64>>>(yp, b2, hp);

    k_pool<<<256, 256>>>();
    k_pick<<<1, 256>>>(node_index);
    k_gemv<<<4, 256>>>(Wg, bg);
    k_final<<<1, 512>>>(eps, out);
}

// round 2
// speedup vs baseline: 1.5031x; 1.5031x over previous
#include <cuda_runtime.h>
#include <cstdint>

// Problem constants (fixed by dataset)
#define NV 100000
#define EV 1600000
#define FV 512
#define HV 256
#define NB_SCAN ((NV + 255) / 256)   // 391

// ---------------- scratch (static device globals; no allocation) ----------------
__device__ int   g_out_deg[NV];
__device__ int   g_in_deg[NV];
__device__ float g_norm_src[NV];
__device__ float g_norm_dst[NV];
__device__ int   g_offsets[NV];
__device__ int   g_cursor[NV];
__device__ int   g_part[NB_SCAN];
__device__ int   g_sorted_src[EV];
__device__ __align__(16) float g_y[(size_t)NV * HV];   // pre-aggregation activations
__device__ __align__(16) float g_h[(size_t)NV * HV];   // post-aggregation activations
__device__ float g_pooled[3 * HV];
__device__ float g_fd[2 * FV];

// ---------------- init / degrees / norms ----------------
__global__ void k_init() {
    int i = blockIdx.x * blockDim.x + threadIdx.x;
    if (i < NV) { g_out_deg[i] = 0; g_in_deg[i] = 0; g_cursor[i] = 0; }
    if (i < HV) { g_pooled[i] = 0.0f; g_pooled[HV + i] = __int_as_float(0xff800000); } // -inf
}

__global__ void k_deg(const int* __restrict__ src, const int* __restrict__ dst) {
    int e = blockIdx.x * blockDim.x + threadIdx.x;
    if (e < EV) {
        atomicAdd(&g_out_deg[src[e]], 1);
        atomicAdd(&g_in_deg[dst[e]], 1);
    }
}

__global__ void k_norm() {
    int i = blockIdx.x * blockDim.x + threadIdx.x;
    if (i < NV) {
        g_norm_src[i] = rsqrtf(fmaxf((float)g_out_deg[i], 1.0f));
        g_norm_dst[i] = rsqrtf(fmaxf((float)g_in_deg[i], 1.0f));
    }
}

// ---------------- exclusive scan of in_deg -> offsets (3 kernels) ----------------
__global__ void k_scan1() {
    __shared__ int s[256];
    int t = threadIdx.x;
    int i = blockIdx.x * 256 + t;
    int v = (i < NV) ? g_in_deg[i] : 0;
    s[t] = v;
    __syncthreads();
    #pragma unroll
    for (int off = 1; off < 256; off <<= 1) {
        int x = (t >= off) ? s[t - off] : 0;
        __syncthreads();
        s[t] += x;
        __syncthreads();
    }
    if (i < NV) g_offsets[i] = s[t] - v;        // exclusive within block
    if (t == 255) g_part[blockIdx.x] = s[255];  // block total
}

// parallel scan of the 391 block totals (was a 1-thread serial loop)
__global__ void k_scan2() {
    __shared__ int s[512];
    int t = threadIdx.x;
    int v = (t < NB_SCAN) ? g_part[t] : 0;
    s[t] = v;
    __syncthreads();
    #pragma unroll
    for (int off = 1; off < 512; off <<= 1) {
        int x = (t >= off) ? s[t - off] : 0;
        __syncthreads();
        s[t] += x;
        __syncthreads();
    }
    if (t < NB_SCAN) g_part[t] = s[t] - v;  // exclusive
}

__global__ void k_scan3() {
    int t = threadIdx.x;
    int i = blockIdx.x * 256 + t;
    if (i < NV) g_offsets[i] += g_part[blockIdx.x];
}

// ---------------- scatter edges into CSR-by-dst ----------------
__global__ void k_scatter(const int* __restrict__ src, const int* __restrict__ dst) {
    int e = blockIdx.x * blockDim.x + threadIdx.x;
    if (e < EV) {
        int d = dst[e];
        int p = atomicAdd(&g_cursor[d], 1);
        g_sorted_src[g_offsets[d] + p] = src[e];
    }
}

// ---------------- tf32 tensor-core GEMM ----------------
// C[M,256] = (A * norm_src[:,None]) @ B[K,256]
// 128x128 block tile, 8 warps (4m x 2n), each warp 32x64 via m16n8k8 tf32 mma.
#define SMS 136   // smem row stride (floats): 136 -> bank = 8*c + r, conflict-free frags

__device__ __forceinline__ uint32_t f2tf(float f) {
    uint32_t u;
    asm("cvt.rna.tf32.f32 %0, %1;" : "=r"(u) : "f"(f));
    return u;
}

__device__ __forceinline__ void mma_tf32(float* c, const uint32_t* a, const uint32_t* b) {
    asm volatile(
        "mma.sync.aligned.m16n8k8.row.col.f32.tf32.tf32.f32 "
        "{%0,%1,%2,%3}, {%4,%5,%6,%7}, {%8,%9}, {%0,%1,%2,%3};"
        : "+f"(c[0]), "+f"(c[1]), "+f"(c[2]), "+f"(c[3])
        : "r"(a[0]), "r"(a[1]), "r"(a[2]), "r"(a[3]), "r"(b[0]), "r"(b[1]));
}

__global__ __launch_bounds__(256) void k_gemm_tf32(const float* __restrict__ A,
                                                   const float* __restrict__ B,
                                                   float* __restrict__ C,
                                                   int M, int K) {
    __shared__ uint32_t As[16 * SMS];   // transposed: [k][m]
    __shared__ uint32_t Bs[16 * SMS];   // [k][n]

    int tid  = threadIdx.x;
    int brow = blockIdx.y * 128;
    int bcol = blockIdx.x * 128;

    // ---- A-load mapping: 128x16 floats = 512 float4, 2 per thread ----
    int arow0 = tid >> 2;               // 0..63
    int arow1 = arow0 + 64;             // 64..127
    int ac0   = (tid & 3) * 4;          // k-offset within tile: 0,4,8,12
    int gr0 = brow + arow0, gr1 = brow + arow1;
    bool v0 = gr0 < M, v1 = gr1 < M;
    float s0 = v0 ? g_norm_src[gr0] : 0.0f;
    float s1 = v1 ? g_norm_src[gr1] : 0.0f;
    const float* Ap0 = A + (size_t)(v0 ? gr0 : 0) * K + ac0;
    const float* Ap1 = A + (size_t)(v1 ? gr1 : 0) * K + ac0;

    // ---- B-load mapping: 16x128 floats = 512 float4, 2 per thread ----
    int bk0 = tid >> 5;                 // 0..7  (second half: +8)
    int bc0 = (tid & 31) * 4;           // 0..124
    const float* Bp0 = B + (size_t)bk0 * HV + bcol + bc0;
    const float* Bp1 = B + (size_t)(bk0 + 8) * HV + bcol + bc0;

    // ---- warp tiling ----
    int wid  = tid >> 5, lane = tid & 31;
    int wm = (wid & 3) * 32;            // warp m offset within block tile
    int wn = (wid >> 2) * 64;           // warp n offset
    int r  = lane >> 2;                 // 0..7
    int cq = lane & 3;                  // 0..3

    float acc[2][8][4];
    #pragma unroll
    for (int i = 0; i < 2; i++)
        #pragma unroll
        for (int j = 0; j < 8; j++)
            #pragma unroll
            for (int q = 0; q < 4; q++) acc[i][j][q] = 0.0f;

    for (int k0 = 0; k0 < K; k0 += 16) {
        // load A tile, scale, convert, store transposed
        {
            float4 a0 = v0 ? *(const float4*)(Ap0 + k0) : make_float4(0,0,0,0);
            float4 a1 = v1 ? *(const float4*)(Ap1 + k0) : make_float4(0,0,0,0);
            As[(ac0 + 0) * SMS + arow0] = f2tf(a0.x * s0);
            As[(ac0 + 1) * SMS + arow0] = f2tf(a0.y * s0);
            As[(ac0 + 2) * SMS + arow0] = f2tf(a0.z * s0);
            As[(ac0 + 3) * SMS + arow0] = f2tf(a0.w * s0);
            As[(ac0 + 0) * SMS + arow1] = f2tf(a1.x * s1);
            As[(ac0 + 1) * SMS + arow1] = f2tf(a1.y * s1);
            As[(ac0 + 2) * SMS + arow1] = f2tf(a1.z * s1);
            As[(ac0 + 3) * SMS + arow1] = f2tf(a1.w * s1);
        }
        // load B tile, convert
        {
            float4 b0 = *(const float4*)(Bp0 + (size_t)k0 * HV);
            float4 b1 = *(const float4*)(Bp1 + (size_t)k0 * HV);
            uint4 u0 = make_uint4(f2tf(b0.x), f2tf(b0.y), f2tf(b0.z), f2tf(b0.w));
            uint4 u1 = make_uint4(f2tf(b1.x), f2tf(b1.y), f2tf(b1.z), f2tf(b1.w));
            *(uint4*)&Bs[bk0 * SMS + bc0]       = u0;
            *(uint4*)&Bs[(bk0 + 8) * SMS + bc0] = u1;
        }
        __syncthreads();

        #pragma unroll
        for (int ks = 0; ks < 2; ks++) {
            uint32_t a[2][4], b[8][2];
            #pragma unroll
            for (int mt = 0; mt < 2; mt++) {
                int mbase = wm + mt * 16 + r;
                a[mt][0] = As[(ks * 8 + cq)     * SMS + mbase];
                a[mt][1] = As[(ks * 8 + cq)     * SMS + mbase + 8];
                a[mt][2] = As[(ks * 8 + cq + 4) * SMS + mbase];
                a[mt][3] = As[(ks * 8 + cq + 4) * SMS + mbase + 8];
            }
            #pragma unroll
            for (int nt = 0; nt < 8; nt++) {
                int nbase = wn + nt * 8 + r;
                b[nt][0] = Bs[(ks * 8 + cq)     * SMS + nbase];
                b[nt][1] = Bs[(ks * 8 + cq + 4) * SMS + nbase];
            }
            #pragma unroll
            for (int mt = 0; mt < 2; mt++)
                #pragma unroll
                for (int nt = 0; nt < 8; nt++)
                    mma_tf32(acc[mt][nt], a[mt], b[nt]);
        }
        __syncthreads();
    }

    // ---- epilogue ----
    #pragma unroll
    for (int mt = 0; mt < 2; mt++) {
        int row0 = brow + wm + mt * 16 + r;
        int row1 = row0 + 8;
        #pragma unroll
        for (int nt = 0; nt < 8; nt++) {
            int col = bcol + wn + nt * 8 + cq * 2;
            if (row0 < M) *(float2*)(C + (size_t)row0 * HV + col) = make_float2(acc[mt][nt][0], acc[mt][nt][1]);
            if (row1 < M) *(float2*)(C + (size_t)row1 * HV + col) = make_float2(acc[mt][nt][2], acc[mt][nt][3]);
        }
    }
}

// ---------------- aggregation: O[n] = leaky( norm_dst[n]*sum_{e in CSR(n)} Y[src_e] + bias ) ----
__global__ void k_agg(const float* __restrict__ Y, const float* __restrict__ bias,
                      float* __restrict__ O) {
    int node = blockIdx.x;
    int t = threadIdx.x;            // 64 threads, 4 cols each via float4
    int start = g_offsets[node];
    int cnt   = g_in_deg[node];
    float4 acc = make_float4(0, 0, 0, 0);
    for (int e = 0; e < cnt; e++) {
        int s = g_sorted_src[start + e];
        float4 v = *(const float4*)(Y + (size_t)s * HV + t * 4);
        acc.x += v.x; acc.y += v.y; acc.z += v.z; acc.w += v.w;
    }
    float nd = g_norm_dst[node];
    float4 bb = *(const float4*)(bias + t * 4);
    float4 o;
    o.x = acc.x * nd + bb.x;  o.x = (o.x >= 0.0f) ? o.x : 0.01f * o.x;
    o.y = acc.y * nd + bb.y;  o.y = (o.y >= 0.0f) ? o.y : 0.01f * o.y;
    o.z = acc.z * nd + bb.z;  o.z = (o.z >= 0.0f) ? o.z : 0.01f * o.z;
    o.w = acc.w * nd + bb.w;  o.w = (o.w >= 0.0f) ? o.w : 0.01f * o.w;
    *(float4*)(O + (size_t)node * HV + t * 4) = o;
}

// ---------------- pooling: column-wise sum and max of g_h ----------------
__device__ __forceinline__ void atomicMaxF(float* addr, float val) {
    int* ia = (int*)addr;
    int old = *ia;
    while (__int_as_float(old) < val) {
        int assumed = old;
        old = atomicCAS(ia, assumed, __float_as_int(val));
        if (old == assumed) break;
    }
}

__global__ void k_pool() {
    int t = threadIdx.x;  // 256
    float sum = 0.0f;
    float mx  = __int_as_float(0xff800000);
    for (int r = blockIdx.x; r < NV; r += gridDim.x) {
        float v = g_h[(size_t)r * HV + t];
        sum += v;
        mx = fmaxf(mx, v);
    }
    atomicAdd(&g_pooled[t], sum);
    atomicMaxF(&g_pooled[HV + t], mx);
}

__global__ void k_pick(const int* __restrict__ node_index) {
    int t = threadIdx.x;  // 256
    int ni = node_index[0];
    g_pooled[2 * HV + t] = g_h[(size_t)ni * HV + t];
}

// ---------------- head GEMV: fd[1024] = pooled[768] @ Wg[768,1024] + bg ----------------
__global__ void k_gemv(const float* __restrict__ Wg, const float* __restrict__ bg) {
    __shared__ float sp[3 * HV];
    int t = threadIdx.x;  // 256, grid 4
    for (int i = t; i < 3 * HV; i += 256) sp[i] = g_pooled[i];
    __syncthreads();
    int j = blockIdx.x * 256 + t;
    float acc = bg[j];
    #pragma unroll 8
    for (int k = 0; k < 3 * HV; k++) acc += sp[k] * Wg[(size_t)k * (2 * FV) + j];
    g_fd[j] = acc;
}

// ---------------- epilogue: reparam + log_prob ----------------
__global__ void k_final(const float* __restrict__ eps, float* __restrict__ out) {
    __shared__ float red[FV];
    int t = threadIdx.x;  // 512
    float mu = g_fd[t];
    float sg = fabsf(g_fd[FV + t]);
    float fn = mu + sg * eps[t];
    out[t]          = fn;   // feat_new
    out[FV + t]     = mu;   // mu
    out[2 * FV + t] = sg;   // sigma
    float z = (fn - mu) / sg;
    const float half_log2pi = 0.9189385332046727f;  // 0.5*log(2*pi)
    float term = -0.5f * z * z - logf(sg) - half_log2pi;
    red[t] = term;
    __syncthreads();
    #pragma unroll
    for (int o = 256; o > 0; o >>= 1) {
        if (t < o) red[t] += red[t + o];
        __syncthreads();
    }
    if (t == 0) out[3 * FV] = red[0] / (float)FV;  // log_prob
}

// ---------------- launch ----------------
extern "C" void kernel_launch(void* const* d_in, const int* in_sizes, int n_in,
                              void* d_out, int out_size) {
    const float* feat       = (const float*)d_in[0];
    const int*   src        = (const int*)  d_in[1];
    const int*   dst        = (const int*)  d_in[2];
    const int*   node_index = (const int*)  d_in[3];
    const float* W1         = (const float*)d_in[4];
    const float* b1         = (const float*)d_in[5];
    const float* W2         = (const float*)d_in[6];
    const float* b2         = (const float*)d_in[7];
    const float* Wg         = (const float*)d_in[8];
    const float* bg         = (const float*)d_in[9];
    const float* eps        = (const float*)d_in[10];
    float*       out        = (float*)d_out;

    void *yp_v, *hp_v;
    cudaGetSymbolAddress(&yp_v, g_y);
    cudaGetSymbolAddress(&hp_v, g_h);
    float* yp = (float*)yp_v;
    float* hp = (float*)hp_v;

    k_init<<<(NV + 255) / 256, 256>>>();
    k_deg<<<(EV + 255) / 256, 256>>>(src, dst);
    k_norm<<<(NV + 255) / 256, 256>>>();
    k_scan1<<<NB_SCAN, 256>>>();
    k_scan2<<<1, 512>>>();
    k_scan3<<<NB_SCAN, 256>>>();
    k_scatter<<<(EV + 255) / 256, 256>>>(src, dst);

    dim3 gemm_grid(2, (NV + 127) / 128);
    // layer 1: y = (feat * norm_src) @ W1 ; h = leaky(agg(y)*norm_dst + b1)
    k_gemm_tf32<<<gemm_grid, 256>>>(feat, W1, yp, NV, FV);
    k_agg<<<NV, 64>>>(yp, b1, hp);
    // layer 2
    k_gemm_tf32<<<gemm_grid, 256>>>(hp, W2, yp, NV, HV);
    k_agg<<<NV, 64>>>(yp, b2, hp);

    k_pool<<<256, 256>>>();
    k_pick<<<1, 256>>>(node_index);
    k_gemv<<<4, 256>>>(Wg, bg);
    k_final<<<1, 512>>>(eps, out);
}

// round 4
// speedup vs baseline: 1.6257x; 1.0815x over previous
#include <cuda_runtime.h>
#include <cstdint>

// Problem constants (fixed by dataset)
#define NV 100000
#define EV 1600000
#define FV 512
#define HV 256
#define NB_SCAN ((NV + 255) / 256)   // 391

// ---------------- scratch (static device globals; no allocation) ----------------
__device__ int   g_out_deg[NV];
__device__ int   g_in_deg[NV];
__device__ float g_norm_src[NV];
__device__ float g_norm_dst[NV];
__device__ int   g_offsets[NV];
__device__ int   g_cursor[NV];
__device__ int   g_part[NB_SCAN];
__device__ int   g_sorted_src[EV];
__device__ __align__(16) float g_y[(size_t)NV * HV];   // pre-aggregation activations (fp32)
__device__ __align__(16) float g_h[(size_t)NV * HV];   // post-aggregation activations
__device__ float g_pooled[3 * HV];
__device__ float g_fd[2 * FV];

// ---------------- init / degrees / norms ----------------
__global__ void k_init() {
    int i = blockIdx.x * blockDim.x + threadIdx.x;
    if (i < NV) { g_out_deg[i] = 0; g_in_deg[i] = 0; g_cursor[i] = 0; }
    if (i < HV) { g_pooled[i] = 0.0f; g_pooled[HV + i] = __int_as_float(0xff800000); } // -inf
}

__global__ void k_deg(const int* __restrict__ src, const int* __restrict__ dst) {
    int e = blockIdx.x * blockDim.x + threadIdx.x;
    if (e < EV) {
        atomicAdd(&g_out_deg[src[e]], 1);
        atomicAdd(&g_in_deg[dst[e]], 1);
    }
}

__global__ void k_norm() {
    int i = blockIdx.x * blockDim.x + threadIdx.x;
    if (i < NV) {
        g_norm_src[i] = rsqrtf(fmaxf((float)g_out_deg[i], 1.0f));
        g_norm_dst[i] = rsqrtf(fmaxf((float)g_in_deg[i], 1.0f));
    }
}

// ---------------- exclusive scan of in_deg -> offsets (3 kernels) ----------------
__global__ void k_scan1() {
    __shared__ int s[256];
    int t = threadIdx.x;
    int i = blockIdx.x * 256 + t;
    int v = (i < NV) ? g_in_deg[i] : 0;
    s[t] = v;
    __syncthreads();
    #pragma unroll
    for (int off = 1; off < 256; off <<= 1) {
        int x = (t >= off) ? s[t - off] : 0;
        __syncthreads();
        s[t] += x;
        __syncthreads();
    }
    if (i < NV) g_offsets[i] = s[t] - v;        // exclusive within block
    if (t == 255) g_part[blockIdx.x] = s[255];  // block total
}

__global__ void k_scan2() {
    __shared__ int s[512];
    int t = threadIdx.x;
    int v = (t < NB_SCAN) ? g_part[t] : 0;
    s[t] = v;
    __syncthreads();
    #pragma unroll
    for (int off = 1; off < 512; off <<= 1) {
        int x = (t >= off) ? s[t - off] : 0;
        __syncthreads();
        s[t] += x;
        __syncthreads();
    }
    if (t < NB_SCAN) g_part[t] = s[t] - v;  // exclusive
}

__global__ void k_scan3() {
    int t = threadIdx.x;
    int i = blockIdx.x * 256 + t;
    if (i < NV) g_offsets[i] += g_part[blockIdx.x];
}

// ---------------- scatter edges into CSR-by-dst ----------------
__global__ void k_scatter(const int* __restrict__ src, const int* __restrict__ dst) {
    int e = blockIdx.x * blockDim.x + threadIdx.x;
    if (e < EV) {
        int d = dst[e];
        int p = atomicAdd(&g_cursor[d], 1);
        g_sorted_src[g_offsets[d] + p] = src[e];
    }
}

// ---------------- tf32 tensor-core GEMM (double-buffered, RNA conversion) ----------------
// C[M,256] = ((A @ B) * norm_src[:,None])
// 128x128 block tile, 8 warps (4m x 2n), each warp 32x64 via m16n8k8 tf32 mma.
#define SMS 136   // smem row stride (uint32)

__device__ __forceinline__ uint32_t f2tf(float f) {
    uint32_t u;
    asm("cvt.rna.tf32.f32 %0, %1;" : "=r"(u) : "f"(f));
    return u;
}

__device__ __forceinline__ void mma_tf32(float* c, const uint32_t* a, const uint32_t* b) {
    asm volatile(
        "mma.sync.aligned.m16n8k8.row.col.f32.tf32.tf32.f32 "
        "{%0,%1,%2,%3}, {%4,%5,%6,%7}, {%8,%9}, {%0,%1,%2,%3};"
        : "+f"(c[0]), "+f"(c[1]), "+f"(c[2]), "+f"(c[3])
        : "r"(a[0]), "r"(a[1]), "r"(a[2]), "r"(a[3]), "r"(b[0]), "r"(b[1]));
}

__global__ __launch_bounds__(256) void k_gemm_tf32(const float* __restrict__ A,
                                                   const float* __restrict__ B,
                                                   float* __restrict__ C,
                                                   int M, int K) {
    __shared__ uint32_t As[2][16 * SMS];   // transposed: [k][m]
    __shared__ uint32_t Bs[2][16 * SMS];   // [k][n]

    int tid  = threadIdx.x;
    int brow = blockIdx.y * 128;
    int bcol = blockIdx.x * 128;

    // ---- A-load mapping: 128x16 floats = 512 float4, 2 per thread ----
    int arow0 = tid >> 2;               // 0..63
    int arow1 = arow0 + 64;             // 64..127
    int ac0   = (tid & 3) * 4;          // k-offset within tile: 0,4,8,12
    int gr0 = brow + arow0, gr1 = brow + arow1;
    bool v0 = gr0 < M, v1 = gr1 < M;
    const float* Ap0 = A + (size_t)(v0 ? gr0 : 0) * K + ac0;
    const float* Ap1 = A + (size_t)(v1 ? gr1 : 0) * K + ac0;

    // ---- B-load mapping: 16x128 floats = 512 float4, 2 per thread ----
    int bk0 = tid >> 5;                 // 0..7  (second half: +8)
    int bc0 = (tid & 31) * 4;           // 0..124
    const float* Bp0 = B + (size_t)bk0 * HV + bcol + bc0;
    const float* Bp1 = B + (size_t)(bk0 + 8) * HV + bcol + bc0;

    // ---- warp tiling ----
    int wid  = tid >> 5, lane = tid & 31;
    int wm = (wid & 3) * 32;            // warp m offset within block tile
    int wn = (wid >> 2) * 64;           // warp n offset
    int r  = lane >> 2;                 // 0..7
    int cq = lane & 3;                  // 0..3

    float acc[2][8][4];
    #pragma unroll
    for (int i = 0; i < 2; i++)
        #pragma unroll
        for (int j = 0; j < 8; j++)
            #pragma unroll
            for (int q = 0; q < 4; q++) acc[i][j][q] = 0.0f;

    // initial prefetch (tile k0 = 0)
    float4 pa0 = v0 ? *(const float4*)(Ap0) : make_float4(0,0,0,0);
    float4 pa1 = v1 ? *(const float4*)(Ap1) : make_float4(0,0,0,0);
    float4 pb0 = *(const float4*)(Bp0);
    float4 pb1 = *(const float4*)(Bp1);

    int buf = 0;
    for (int k0 = 0; k0 < K; k0 += 16) {
        // store prefetched tile (RNA-converted to tf32) into smem[buf]
        uint32_t* Asb = As[buf];
        uint32_t* Bsb = Bs[buf];
        Asb[(ac0 + 0) * SMS + arow0] = f2tf(pa0.x);
        Asb[(ac0 + 1) * SMS + arow0] = f2tf(pa0.y);
        Asb[(ac0 + 2) * SMS + arow0] = f2tf(pa0.z);
        Asb[(ac0 + 3) * SMS + arow0] = f2tf(pa0.w);
        Asb[(ac0 + 0) * SMS + arow1] = f2tf(pa1.x);
        Asb[(ac0 + 1) * SMS + arow1] = f2tf(pa1.y);
        Asb[(ac0 + 2) * SMS + arow1] = f2tf(pa1.z);
        Asb[(ac0 + 3) * SMS + arow1] = f2tf(pa1.w);
        *(uint4*)&Bsb[bk0 * SMS + bc0]       = make_uint4(f2tf(pb0.x), f2tf(pb0.y), f2tf(pb0.z), f2tf(pb0.w));
        *(uint4*)&Bsb[(bk0 + 8) * SMS + bc0] = make_uint4(f2tf(pb1.x), f2tf(pb1.y), f2tf(pb1.z), f2tf(pb1.w));
        __syncthreads();

        // prefetch next tile while computing this one
        int kn = k0 + 16;
        if (kn < K) {
            pa0 = v0 ? *(const float4*)(Ap0 + kn) : make_float4(0,0,0,0);
            pa1 = v1 ? *(const float4*)(Ap1 + kn) : make_float4(0,0,0,0);
            pb0 = *(const float4*)(Bp0 + (size_t)kn * HV);
            pb1 = *(const float4*)(Bp1 + (size_t)kn * HV);
        }

        #pragma unroll
        for (int ks = 0; ks < 2; ks++) {
            uint32_t a[2][4], b[8][2];
            #pragma unroll
            for (int mt = 0; mt < 2; mt++) {
                int mbase = wm + mt * 16 + r;
                a[mt][0] = Asb[(ks * 8 + cq)     * SMS + mbase];
                a[mt][1] = Asb[(ks * 8 + cq)     * SMS + mbase + 8];
                a[mt][2] = Asb[(ks * 8 + cq + 4) * SMS + mbase];
                a[mt][3] = Asb[(ks * 8 + cq + 4) * SMS + mbase + 8];
            }
            #pragma unroll
            for (int nt = 0; nt < 8; nt++) {
                int nbase = wn + nt * 8 + r;
                b[nt][0] = Bsb[(ks * 8 + cq)     * SMS + nbase];
                b[nt][1] = Bsb[(ks * 8 + cq + 4) * SMS + nbase];
            }
            #pragma unroll
            for (int mt = 0; mt < 2; mt++)
                #pragma unroll
                for (int nt = 0; nt < 8; nt++)
                    mma_tf32(acc[mt][nt], a[mt], b[nt]);
        }
        buf ^= 1;
        __syncthreads();
    }

    // ---- epilogue: scale by norm_src[row], store fp32 ----
    #pragma unroll
    for (int mt = 0; mt < 2; mt++) {
        int row0 = brow + wm + mt * 16 + r;
        int row1 = row0 + 8;
        float s0 = (row0 < M) ? g_norm_src[row0] : 0.0f;
        float s1 = (row1 < M) ? g_norm_src[row1] : 0.0f;
        #pragma unroll
        for (int nt = 0; nt < 8; nt++) {
            int col = bcol + wn + nt * 8 + cq * 2;
            if (row0 < M) *(float2*)(C + (size_t)row0 * HV + col) =
                make_float2(acc[mt][nt][0] * s0, acc[mt][nt][1] * s0);
            if (row1 < M) *(float2*)(C + (size_t)row1 * HV + col) =
                make_float2(acc[mt][nt][2] * s1, acc[mt][nt][3] * s1);
        }
    }
}

// ---------------- aggregation: O[n] = leaky( norm_dst[n]*sum_{e in CSR(n)} Y[src_e] + bias ) ----
// 64 threads per node, 4 fp32 cols each via float4; 2-way unrolled dual accumulators.
__global__ void k_agg(const float* __restrict__ Y, const float* __restrict__ bias,
                      float* __restrict__ O) {
    int node = blockIdx.x;
    int t = threadIdx.x;            // 0..63
    int start = g_offsets[node];
    int cnt   = g_in_deg[node];

    float a0 = 0.f, a1 = 0.f, a2 = 0.f, a3 = 0.f;
    float b0 = 0.f, b1 = 0.f, b2 = 0.f, b3 = 0.f;
    int e = 0;
    for (; e + 2 <= cnt; e += 2) {
        int s0 = g_sorted_src[start + e];
        int s1 = g_sorted_src[start + e + 1];
        float4 x = *(const float4*)(Y + (size_t)s0 * HV + t * 4);
        float4 y = *(const float4*)(Y + (size_t)s1 * HV + t * 4);
        a0 += x.x; a1 += x.y; a2 += x.z; a3 += x.w;
        b0 += y.x; b1 += y.y; b2 += y.z; b3 += y.w;
    }
    if (e < cnt) {
        int s0 = g_sorted_src[start + e];
        float4 x = *(const float4*)(Y + (size_t)s0 * HV + t * 4);
        a0 += x.x; a1 += x.y; a2 += x.z; a3 += x.w;
    }
    a0 += b0; a1 += b1; a2 += b2; a3 += b3;

    float nd = g_norm_dst[node];
    float4 bb = *(const float4*)(bias + t * 4);
    float4 o;
    o.x = a0 * nd + bb.x;  o.x = (o.x >= 0.0f) ? o.x : 0.01f * o.x;
    o.y = a1 * nd + bb.y;  o.y = (o.y >= 0.0f) ? o.y : 0.01f * o.y;
    o.z = a2 * nd + bb.z;  o.z = (o.z >= 0.0f) ? o.z : 0.01f * o.z;
    o.w = a3 * nd + bb.w;  o.w = (o.w >= 0.0f) ? o.w : 0.01f * o.w;
    *(float4*)(O + (size_t)node * HV + t * 4) = o;
}

// ---------------- pooling: column-wise sum and max of g_h ----------------
__device__ __forceinline__ void atomicMaxF(float* addr, float val) {
    int* ia = (int*)addr;
    int old = *ia;
    while (__int_as_float(old) < val) {
        int assumed = old;
        old = atomicCAS(ia, assumed, __float_as_int(val));
        if (old == assumed) break;
    }
}

__global__ void k_pool() {
    int t = threadIdx.x;  // 256
    float sum = 0.0f;
    float mx  = __int_as_float(0xff800000);
    for (int r = blockIdx.x; r < NV; r += gridDim.x) {
        float v = g_h[(size_t)r * HV + t];
        sum += v;
        mx = fmaxf(mx, v);
    }
    atomicAdd(&g_pooled[t], sum);
    atomicMaxF(&g_pooled[HV + t], mx);
}

__global__ void k_pick(const int* __restrict__ node_index) {
    int t = threadIdx.x;  // 256
    int ni = node_index[0];
    g_pooled[2 * HV + t] = g_h[(size_t)ni * HV + t];
}

// ---------------- head GEMV: fd[1024] = pooled[768] @ Wg[768,1024] + bg ----------------
__global__ void k_gemv(const float* __restrict__ Wg, const float* __restrict__ bg) {
    __shared__ float sp[3 * HV];
    int t = threadIdx.x;  // 256, grid 4
    for (int i = t; i < 3 * HV; i += 256) sp[i] = g_pooled[i];
    __syncthreads();
    int j = blockIdx.x * 256 + t;
    float acc = bg[j];
    #pragma unroll 8
    for (int k = 0; k < 3 * HV; k++) acc += sp[k] * Wg[(size_t)k * (2 * FV) + j];
    g_fd[j] = acc;
}

// ---------------- epilogue: reparam + log_prob ----------------
__global__ void k_final(const float* __restrict__ eps, float* __restrict__ out) {
    __shared__ float red[FV];
    int t = threadIdx.x;  // 512
    float mu = g_fd[t];
    float sg = fabsf(g_fd[FV + t]);
    float fn = mu + sg * eps[t];
    out[t]          = fn;   // feat_new
    out[FV + t]     = mu;   // mu
    out[2 * FV + t] = sg;   // sigma
    float z = (fn - mu) / sg;
    const float half_log2pi = 0.9189385332046727f;  // 0.5*log(2*pi)
    float term = -0.5f * z * z - logf(sg) - half_log2pi;
    red[t] = term;
    __syncthreads();
    #pragma unroll
    for (int o = 256; o > 0; o >>= 1) {
        if (t < o) red[t] += red[t + o];
        __syncthreads();
    }
    if (t == 0) out[3 * FV] = red[0] / (float)FV;  // log_prob
}

// ---------------- launch ----------------
extern "C" void kernel_launch(void* const* d_in, const int* in_sizes, int n_in,
                              void* d_out, int out_size) {
    const float* feat       = (const float*)d_in[0];
    const int*   src        = (const int*)  d_in[1];
    const int*   dst        = (const int*)  d_in[2];
    const int*   node_index = (const int*)  d_in[3];
    const float* W1         = (const float*)d_in[4];
    const float* b1         = (const float*)d_in[5];
    const float* W2         = (const float*)d_in[6];
    const float* b2         = (const float*)d_in[7];
    const float* Wg         = (const float*)d_in[8];
    const float* bg         = (const float*)d_in[9];
    const float* eps        = (const float*)d_in[10];
    float*       out        = (float*)d_out;

    void *yp_v, *hp_v;
    cudaGetSymbolAddress(&yp_v, g_y);
    cudaGetSymbolAddress(&hp_v, g_h);
    float* yp = (float*)yp_v;
    float* hp = (float*)hp_v;

    dim3 gemm_grid(2, (NV + 127) / 128);

    k_init<<<(NV + 255) / 256, 256>>>();
    k_deg<<<(EV + 255) / 256, 256>>>(src, dst);
    k_norm<<<(NV + 255) / 256, 256>>>();
    // GEMM1 early (launch #4) so the fixed-index ncu capture profiles it
    k_gemm_tf32<<<gemm_grid, 256>>>(feat, W1, yp, NV, FV);
    k_scan1<<<NB_SCAN, 256>>>();
    k_scan2<<<1, 512>>>();
    k_scan3<<<NB_SCAN, 256>>>();
    k_scatter<<<(EV + 255) / 256, 256>>>(src, dst);

    k_agg<<<NV, 64>>>(yp, b1, hp);
    k_gemm_tf32<<<gemm_grid, 256>>>(hp, W2, yp, NV, HV);
    k_agg<<<NV, 64>>>(yp, b2, hp);

    k_pool<<<256, 256>>>();
    k_pick<<<1, 256>>>(node_index);
    k_gemv<<<4, 256>>>(Wg, bg);
    k_final<<<1, 512>>>(eps, out);
}